// round 1
// baseline (speedup 1.0000x reference)
#include <cuda_runtime.h>

#define N       4096
#define WPB     16            // warps per block (1 row per warp)
#define TPB     (WPB * 32)    // 512 threads
#define NBLK    (N / WPB)     // 256 blocks
#define TILE    2048          // target boxes per smem tile (2 tiles total)
#define FTPB    512           // epilogue threads

// Scratch (device globals — no allocation allowed)
__device__ float  g_maxov[N];
__device__ int    g_arg[N];
__device__ double g_bsum[NBLK];
__device__ int    g_bcnt[NBLK];

// ---------------------------------------------------------------------------
// Kernel 1: all-pairs IoU. Per row: masked max/argmax (RepGT candidate).
// Per block: partial RepBox sum/count (tril & !same_tgt & ov>0; sigma=0 so
// smooth_ln(ov,0) == ov).
// ---------------------------------------------------------------------------
__global__ __launch_bounds__(TPB) void pair_kernel(const float4* __restrict__ pred,
                                                   const float4* __restrict__ tgt)
{
    __shared__ float4 s_t[TILE];
    __shared__ float  s_a[TILE];
    __shared__ double s_wsum[WPB];
    __shared__ int    s_wcnt[WPB];

    const int warp = threadIdx.x >> 5;
    const int lane = threadIdx.x & 31;
    const int row  = blockIdx.x * WPB + warp;

    const float4 p  = pred[row];
    const float4 ti = tgt[row];
    const float area_a = (p.z - p.x + 1.0f) * (p.w - p.y + 1.0f);

    float best  = 0.0f;   // max masked IoU for this row
    int   bestj = 0;      // first argmax (jnp.argmax semantics)
    float bsum  = 0.0f;   // repbox partial sum (j < row)
    int   bcnt  = 0;

    for (int t0 = 0; t0 < N; t0 += TILE) {
        __syncthreads();
        for (int k = threadIdx.x; k < TILE; k += TPB) {
            float4 t = tgt[t0 + k];
            s_t[k] = t;
            s_a[k] = (t.z - t.x + 1.0f) * (t.w - t.y + 1.0f);
        }
        __syncthreads();

        #pragma unroll 8
        for (int k = lane; k < TILE; k += 32) {
            const float4 t = s_t[k];
            const int j = t0 + k;
            // +1 pixel convention intersection
            float iw = fminf(p.z, t.z) - fmaxf(p.x, t.x) + 1.0f;
            float ih = fminf(p.w, t.w) - fmaxf(p.y, t.y) + 1.0f;
            iw = fmaxf(iw, 0.0f);
            ih = fmaxf(ih, 0.0f);
            const float inter = iw * ih;
            const bool same = (ti.x == t.x) && (ti.y == t.y) &&
                              (ti.z == t.z) && (ti.w == t.w);
            if (inter > 0.0f && !same) {          // ~3% of pairs take this path
                const float ua = area_a + s_a[k] - inter;   // ua > 0 always
                const float ov = inter / ua;                 // IEEE div (matches XLA)
                if (ov > best) { best = ov; bestj = j; }     // strict > keeps first idx
                if (j < row)   { bsum += ov; bcnt++; }       // tril (k=-1)
            }
        }
    }

    // Warp reductions: max/argmax with first-index tie break, sum, count.
    #pragma unroll
    for (int off = 16; off; off >>= 1) {
        float ov2 = __shfl_down_sync(0xffffffffu, best,  off);
        int   j2  = __shfl_down_sync(0xffffffffu, bestj, off);
        bsum     += __shfl_down_sync(0xffffffffu, bsum,  off);
        bcnt     += __shfl_down_sync(0xffffffffu, bcnt,  off);
        if (ov2 > best || (ov2 == best && j2 < bestj)) { best = ov2; bestj = j2; }
    }
    if (lane == 0) {
        g_maxov[row] = best;
        g_arg[row]   = bestj;
        s_wsum[warp] = (double)bsum;
        s_wcnt[warp] = bcnt;
    }
    __syncthreads();
    if (threadIdx.x == 0) {
        double s = 0.0; int c = 0;
        #pragma unroll
        for (int w = 0; w < WPB; w++) { s += s_wsum[w]; c += s_wcnt[w]; }
        g_bsum[blockIdx.x] = s;     // deterministic per-block slot (no float atomics)
        g_bcnt[blockIdx.x] = c;
    }
}

// ---------------------------------------------------------------------------
// Kernel 2: single-block epilogue. Deterministic reduction of repbox partials,
// smooth-L1 mean, RepGT (iog + smooth_ln sigma=0.9), final scalar broadcast.
// ---------------------------------------------------------------------------
__device__ __forceinline__ double block_reduce_d(double v, double* sh, int tid)
{
    sh[tid] = v; __syncthreads();
    #pragma unroll
    for (int s = FTPB / 2; s > 0; s >>= 1) {
        if (tid < s) sh[tid] += sh[tid + s];
        __syncthreads();
    }
    double r = sh[0]; __syncthreads();
    return r;
}

__device__ __forceinline__ int block_reduce_i(int v, int* sh, int tid)
{
    sh[tid] = v; __syncthreads();
    #pragma unroll
    for (int s = FTPB / 2; s > 0; s >>= 1) {
        if (tid < s) sh[tid] += sh[tid + s];
        __syncthreads();
    }
    int r = sh[0]; __syncthreads();
    return r;
}

__global__ __launch_bounds__(FTPB) void final_kernel(const float* __restrict__ predf,
                                                     const float* __restrict__ tgtf,
                                                     float* __restrict__ out)
{
    __shared__ double shd[FTPB];
    __shared__ int    shi[FTPB];
    __shared__ float  s_scalar;

    const int tid = threadIdx.x;
    const float4* pred = (const float4*)predf;
    const float4* tgt  = (const float4*)tgtf;

    // RepBox: fixed-order reduce of per-block partials
    double bsum = 0.0; int bcnt = 0;
    for (int b = tid; b < NBLK; b += FTPB) { bsum += g_bsum[b]; bcnt += g_bcnt[b]; }

    // Smooth-L1 (beta = 1, mean over N*4 elements)
    double s1 = 0.0;
    for (int e = tid; e < N * 4; e += FTPB) {
        float d = fabsf(predf[e] - tgtf[e]);
        float v = (d < 1.0f) ? 0.5f * d * d : d - 0.5f;
        s1 += (double)v;
    }

    // RepGT: iog(pred_i, target[argmax]) + smooth_ln(sigma=0.9) where max_ov > 0
    double gsum = 0.0; int gcnt = 0;
    for (int i = tid; i < N; i += FTPB) {
        const float mo = g_maxov[i];
        if (mo > 0.0f) {
            const float4 p = pred[i];
            const float4 g = tgt[g_arg[i]];
            float iw = fmaxf(fminf(p.z, g.z) - fmaxf(p.x, g.x), 0.0f);  // no +1
            float ih = fmaxf(fminf(p.w, g.w) - fmaxf(p.y, g.y), 0.0f);
            const float garea = (g.z - g.x) * (g.w - g.y);
            const float x = iw * ih / garea;
            float v;
            if (x > 0.9f) {
                v = (x - 0.9f) / (1.0f - 0.9f) + 2.3025851f;  // -float32(log1p(-0.9))
            } else {
                float xc = fminf(fmaxf(x, 0.0f), 1.0f - 1e-6f);
                v = -log1pf(-xc);
            }
            gsum += (double)v;
            gcnt++;
        }
    }

    const double BSUM = block_reduce_d(bsum, shd, tid);
    const int    BCNT = block_reduce_i(bcnt, shi, tid);
    const double S1   = block_reduce_d(s1,   shd, tid);
    const double GSUM = block_reduce_d(gsum, shd, tid);
    const int    GCNT = block_reduce_i(gcnt, shi, tid);

    if (tid == 0) {
        float sl1    = (float)(S1 / (double)(N * 4));
        float repgt  = (GCNT > 0) ? (float)(GSUM / (double)GCNT) : 0.0f;
        float repbox = (BCNT > 0) ? (float)(BSUM / (double)BCNT) : 0.0f;
        s_scalar = sl1 + repgt + repbox;   // LOSS_WEIGHT = 1 everywhere
    }
    __syncthreads();

    const float sc = s_scalar;
    for (int i = tid; i < N; i += FTPB) out[i] = sc;
}

// ---------------------------------------------------------------------------
extern "C" void kernel_launch(void* const* d_in, const int* in_sizes, int n_in,
                              void* d_out, int out_size)
{
    const float* pred = (const float*)d_in[0];
    const float* tgt  = (const float*)d_in[1];
    float* out = (float*)d_out;

    pair_kernel<<<NBLK, TPB>>>((const float4*)pred, (const float4*)tgt);
    final_kernel<<<1, FTPB>>>(pred, tgt, out);
}

// round 5
// speedup vs baseline: 2.0292x; 2.0292x over previous
#include <cuda_runtime.h>

#define N        4096
#define WPB      16                   // warps per block
#define TPB      (WPB * 32)           // 512 threads
#define RPW      2                    // rows per warp
#define NBLK     (N / (WPB * RPW))    // 128 blocks -> single wave on 148 SMs
#define TILE     2048                 // target boxes per smem tile (2 tiles)

// Scratch slots (device globals; g_done reset by last block each call)
__device__ float g_bs[NBLK];   // repbox sum partial
__device__ int   g_bc[NBLK];   // repbox count partial
__device__ float g_gs[NBLK];   // repgt  sum partial
__device__ int   g_gc[NBLK];   // repgt  count partial
__device__ float g_s1[NBLK];   // smooth-L1 partial
__device__ int   g_done;

__global__ __launch_bounds__(TPB, 1)
void repulsion_kernel(const float4* __restrict__ pred,
                      const float4* __restrict__ tgt,
                      const float*  __restrict__ predf,
                      const float*  __restrict__ tgtf,
                      float*        __restrict__ out)
{
    __shared__ float4 s_t[TILE];          // (tx, ty, tz+1, tw+1)
    __shared__ float  s_a[TILE];          // +1-convention area
    __shared__ float  s_wf[2 * WPB];      // per-warp bsum, gsum
    __shared__ int    s_wi[2 * WPB];      // per-warp bcnt, gcnt
    __shared__ float  s_s1w[WPB];
    __shared__ float  s_scalar;
    __shared__ int    s_last;

    const int tid  = threadIdx.x;
    const int warp = tid >> 5;
    const int lane = tid & 31;
    const int r0   = (blockIdx.x * WPB + warp) * RPW;
    const int r1   = r0 + 1;

    // Row constants (originals kept for the IoG epilogue)
    const float4 p0 = pred[r0];
    const float4 p1 = pred[r1];
    const float p0z1 = p0.z + 1.0f, p0w1 = p0.w + 1.0f;
    const float p1z1 = p1.z + 1.0f, p1w1 = p1.w + 1.0f;
    const float a0 = (p0z1 - p0.x) * (p0w1 - p0.y);
    const float a1 = (p1z1 - p1.x) * (p1w1 - p1.y);

    float best0 = 0.0f, best1 = 0.0f;
    int   bj0 = 0, bj1 = 0;
    float bsum = 0.0f;
    int   bcnt = 0;

    for (int t0 = 0; t0 < N; t0 += TILE) {
        __syncthreads();
        for (int k = tid; k < TILE; k += TPB) {
            float4 t = tgt[t0 + k];
            t.z += 1.0f; t.w += 1.0f;
            s_t[k] = t;
            s_a[k] = (t.z - t.x) * (t.w - t.y);
        }
        __syncthreads();

        #pragma unroll 8
        for (int k = lane; k < TILE; k += 32) {
            const float4 t  = s_t[k];
            const float  ta = s_a[k];
            const int    j  = t0 + k;
            const bool lt0  = j < r0;        // tril predicates (fold w/ unroll)
            const bool lt1  = j < r1;
            const bool ne0  = j != r0;       // same_tgt <=> j==row (unique tgts)
            const bool ne1  = j != r1;

            // ---- row 0 ----
            {
                float iw = fmaxf(fminf(p0z1, t.z) - fmaxf(p0.x, t.x), 0.0f);
                float ih = fmaxf(fminf(p0w1, t.w) - fmaxf(p0.y, t.y), 0.0f);
                float inter = iw * ih;
                float ov = __fdividef(inter, (a0 + ta) - inter); // 0 if inter==0
                if (ne0 & (ov > best0)) { best0 = ov; bj0 = j; }
                bool tb = lt0 & (ov > 0.0f);
                bsum += tb ? ov : 0.0f;
                bcnt += tb ? 1 : 0;
            }
            // ---- row 1 ----
            {
                float iw = fmaxf(fminf(p1z1, t.z) - fmaxf(p1.x, t.x), 0.0f);
                float ih = fmaxf(fminf(p1w1, t.w) - fmaxf(p1.y, t.y), 0.0f);
                float inter = iw * ih;
                float ov = __fdividef(inter, (a1 + ta) - inter);
                if (ne1 & (ov > best1)) { best1 = ov; bj1 = j; }
                bool tb = lt1 & (ov > 0.0f);
                bsum += tb ? ov : 0.0f;
                bcnt += tb ? 1 : 0;
            }
        }
    }

    // Warp reductions: max/argmax (first-index ties) per row, sums.
    #pragma unroll
    for (int off = 16; off; off >>= 1) {
        float b0 = __shfl_down_sync(0xffffffffu, best0, off);
        int   j0 = __shfl_down_sync(0xffffffffu, bj0,   off);
        float b1 = __shfl_down_sync(0xffffffffu, best1, off);
        int   j1 = __shfl_down_sync(0xffffffffu, bj1,   off);
        bsum    += __shfl_down_sync(0xffffffffu, bsum,  off);
        bcnt    += __shfl_down_sync(0xffffffffu, bcnt,  off);
        if (b0 > best0 || (b0 == best0 && j0 < bj0)) { best0 = b0; bj0 = j0; }
        if (b1 > best1 || (b1 == best1 && j1 < bj1)) { best1 = b1; bj1 = j1; }
    }

    if (lane == 0) {
        // RepGT terms for this warp's two rows (rare path, exact math)
        float gs = 0.0f; int gc = 0;
        #pragma unroll
        for (int r = 0; r < 2; r++) {
            const float best = r ? best1 : best0;
            if (best > 0.0f) {
                const float4 p = r ? p1 : p0;
                const float4 g = tgt[r ? bj1 : bj0];
                float iw = fmaxf(fminf(p.z, g.z) - fmaxf(p.x, g.x), 0.0f); // no +1
                float ih = fmaxf(fminf(p.w, g.w) - fmaxf(p.y, g.y), 0.0f);
                float x  = iw * ih / ((g.z - g.x) * (g.w - g.y));
                float v;
                if (x > 0.9f) {
                    v = (x - 0.9f) / (1.0f - 0.9f) + 2.30258509f; // -f32(log1p(-0.9))
                } else {
                    float xc = fminf(fmaxf(x, 0.0f), 1.0f - 1e-6f);
                    v = -log1pf(-xc);
                }
                gs += v; gc++;
            }
        }
        s_wf[warp]       = bsum;
        s_wf[WPB + warp] = gs;
        s_wi[warp]       = bcnt;
        s_wi[WPB + warp] = gc;
    }

    // Smooth-L1 partial: this block owns 32 rows -> 128 elements
    {
        float s1 = 0.0f;
        if (tid < WPB * RPW * 4) {
            const int e = blockIdx.x * (WPB * RPW * 4) + tid;
            float d = fabsf(predf[e] - tgtf[e]);
            s1 = (d < 1.0f) ? 0.5f * d * d : d - 0.5f;
        }
        #pragma unroll
        for (int off = 16; off; off >>= 1)
            s1 += __shfl_down_sync(0xffffffffu, s1, off);
        if (lane == 0) s_s1w[warp] = s1;
    }
    __syncthreads();

    if (tid == 0) {
        float BS = 0.0f, GS = 0.0f, S1 = 0.0f; int BC = 0, GC = 0;
        #pragma unroll
        for (int w = 0; w < WPB; w++) {
            BS += s_wf[w]; GS += s_wf[WPB + w];
            BC += s_wi[w]; GC += s_wi[WPB + w];
            S1 += s_s1w[w];
        }
        g_bs[blockIdx.x] = BS; g_gs[blockIdx.x] = GS; g_s1[blockIdx.x] = S1;
        g_bc[blockIdx.x] = BC; g_gc[blockIdx.x] = GC;
        __threadfence();
        int prev = atomicAdd(&g_done, 1);
        s_last = (prev == NBLK - 1);
    }
    __syncthreads();
    if (!s_last) return;

    // ---- last block: deterministic 128-slot reduction + broadcast ----
    if (warp == 0) {
        float BS = 0.0f, GS = 0.0f, S1 = 0.0f; int BC = 0, GC = 0;
        for (int i = lane; i < NBLK; i += 32) {   // fixed order per lane
            BS += g_bs[i]; GS += g_gs[i]; S1 += g_s1[i];
            BC += g_bc[i]; GC += g_gc[i];
        }
        #pragma unroll
        for (int off = 16; off; off >>= 1) {
            BS += __shfl_down_sync(0xffffffffu, BS, off);
            GS += __shfl_down_sync(0xffffffffu, GS, off);
            S1 += __shfl_down_sync(0xffffffffu, S1, off);
            BC += __shfl_down_sync(0xffffffffu, BC, off);
            GC += __shfl_down_sync(0xffffffffu, GC, off);
        }
        if (lane == 0) {
            float sl1    = S1 / (float)(N * 4);
            float repgt  = (GC > 0) ? GS / (float)GC : 0.0f;
            float repbox = (BC > 0) ? BS / (float)BC : 0.0f;
            s_scalar = sl1 + repgt + repbox;   // LOSS_WEIGHT = 1
            g_done = 0;                        // reset for next graph replay
        }
    }
    __syncthreads();
    const float sc = s_scalar;
    for (int i = tid; i < N; i += TPB) out[i] = sc;
}

extern "C" void kernel_launch(void* const* d_in, const int* in_sizes, int n_in,
                              void* d_out, int out_size)
{
    const float* pred = (const float*)d_in[0];
    const float* tgt  = (const float*)d_in[1];
    float* out = (float*)d_out;

    repulsion_kernel<<<NBLK, TPB>>>((const float4*)pred, (const float4*)tgt,
                                    pred, tgt, out);
}